// round 5
// baseline (speedup 1.0000x reference)
#include <cuda_runtime.h>
#include <cstdint>

// Problem constants (fixed by the dataset)
#define MROWS 8192
#define NCOLS 8192
#define KROWS 8192
#define NNZ   256
#define BATCH 32

// Warps 0..QUAD_WARPS-1 of each CTA run quad-line mode (wavefront-pipe heavy),
// the rest run single-line mode (LSU-dispatch heavy). Mixing loads both SM
// resources concurrently: calibrated model predicts ~2.04 cyc/nnz vs 2.45
// (pure quad, R4) and 2.73 (pure single, R2).
#define QUAD_WARPS 4

// Intermediate bx = B @ x, [KROWS, BATCH] row-major. 1 MB device-global scratch.
__device__ float g_bx[KROWS * BATCH];

template<int OUT_TRANSPOSED>
__global__ void __launch_bounds__(256)
ell_spmm_kernel(const int*   __restrict__ idx,
                const float* __restrict__ vals,
                const float* __restrict__ src,
                float*       __restrict__ dst)
{
    // Interleaved (idx, val_bits) pairs, one row per warp. 16B-aligned so the
    // single-mode path can read two pairs per LDS.128.
    __shared__ __align__(16) uint2 s_pair[8][NNZ];

    const int warp = threadIdx.x >> 5;
    const int lane = threadIdx.x & 31;
    const int row  = blockIdx.x * 8 + warp;

    // Stage metadata: coalesced int4/float4 global loads, interleaved smem writes.
    {
        const int4*   ip = reinterpret_cast<const int4*>(idx  + (size_t)row * NNZ);
        const float4* vp = reinterpret_cast<const float4*>(vals + (size_t)row * NNZ);
#pragma unroll
        for (int q = 0; q < NNZ / (32 * 4); ++q) {
            const int4   iv = ip[q * 32 + lane];
            const float4 vv = vp[q * 32 + lane];
            const int base = (q * 32 + lane) * 4;
            s_pair[warp][base + 0] = make_uint2((unsigned)iv.x, __float_as_uint(vv.x));
            s_pair[warp][base + 1] = make_uint2((unsigned)iv.y, __float_as_uint(vv.y));
            s_pair[warp][base + 2] = make_uint2((unsigned)iv.z, __float_as_uint(vv.z));
            s_pair[warp][base + 3] = make_uint2((unsigned)iv.w, __float_as_uint(vv.w));
        }
    }
    __syncwarp();

    if (warp < QUAD_WARPS) {
        // ── Quad-line mode: 4 subgroups of 8 lanes; one LDG.128 gathers 4
        //    distinct fully-used 128B lines (4 nnz). LDS.64 with 4 broadcast
        //    groups serves metadata for 4 nnz per wavefront.
        const int g = lane >> 3;   // nnz subgroup 0..3
        const int c = lane & 7;    // batch quad 0..7

        const float4* src4 = reinterpret_cast<const float4*>(src) + c;
        float4 acc = make_float4(0.f, 0.f, 0.f, 0.f);

#pragma unroll 4
        for (int t = 0; t < NNZ / 4; ++t) {
            const uint2  p = s_pair[warp][t * 4 + g];
            const float4 d = __ldg(&src4[(size_t)p.x * (BATCH / 4)]);
            const float  v = __uint_as_float(p.y);
            acc.x = fmaf(v, d.x, acc.x);
            acc.y = fmaf(v, d.y, acc.y);
            acc.z = fmaf(v, d.z, acc.z);
            acc.w = fmaf(v, d.w, acc.w);
        }

        // Reduce over the 4 nnz subgroups (lanes 8 apart share batch quad c).
#pragma unroll
        for (int off = 8; off < 32; off <<= 1) {
            acc.x += __shfl_xor_sync(0xffffffffu, acc.x, off);
            acc.y += __shfl_xor_sync(0xffffffffu, acc.y, off);
            acc.z += __shfl_xor_sync(0xffffffffu, acc.z, off);
            acc.w += __shfl_xor_sync(0xffffffffu, acc.w, off);
        }

        if (g == 0) {
            if (OUT_TRANSPOSED) {
                dst[(size_t)(4 * c + 0) * MROWS + row] = acc.x;
                dst[(size_t)(4 * c + 1) * MROWS + row] = acc.y;
                dst[(size_t)(4 * c + 2) * MROWS + row] = acc.z;
                dst[(size_t)(4 * c + 3) * MROWS + row] = acc.w;
            } else {
                reinterpret_cast<float4*>(dst + (size_t)row * BATCH)[c] = acc;
            }
        }
    } else {
        // ── Single-line mode: lane == batch column; one LDG.32 per nnz
        //    (one coalesced 128B line, cross-LDG wavefronts at ~1/cyc).
        //    Metadata: two pairs per LDS.128 broadcast.
        const uint4* sp   = reinterpret_cast<const uint4*>(s_pair[warp]);
        const float* srcl = src + lane;
        float acc0 = 0.0f, acc1 = 0.0f;

#pragma unroll 4
        for (int t = 0; t < NNZ / 2; ++t) {
            const uint4 p = sp[t];   // {idx0, val0, idx1, val1}
            acc0 = fmaf(__uint_as_float(p.y), __ldg(&srcl[(size_t)p.x * BATCH]), acc0);
            acc1 = fmaf(__uint_as_float(p.w), __ldg(&srcl[(size_t)p.z * BATCH]), acc1);
        }
        const float acc = acc0 + acc1;

        if (OUT_TRANSPOSED)
            dst[(size_t)lane * MROWS + row] = acc;   // out[b][m]
        else
            dst[(size_t)row * BATCH + lane] = acc;   // bx[k][b]
    }
}

extern "C" void kernel_launch(void* const* d_in, const int* in_sizes, int n_in,
                              void* d_out, int out_size)
{
    // metadata order:
    //   0: x      float32 [8192, 32]
    //   1: a_idx  int32   [8192, 256]
    //   2: a_vals float32 [8192, 256]
    //   3: b_idx  int32   [8192, 256]
    //   4: b_vals float32 [8192, 256]
    const float* x      = (const float*)d_in[0];
    const int*   a_idx  = (const int*)  d_in[1];
    const float* a_vals = (const float*)d_in[2];
    const int*   b_idx  = (const int*)  d_in[3];
    const float* b_vals = (const float*)d_in[4];
    float* out = (float*)d_out;  // (1, 32, 8192) fp32

    float* bx;
    cudaGetSymbolAddress((void**)&bx, g_bx);

    // Stage 1: bx = B @ x
    ell_spmm_kernel<0><<<KROWS / 8, 256>>>(b_idx, b_vals, x, bx);
    // Stage 2: out = (A @ bx)^T
    ell_spmm_kernel<1><<<MROWS / 8, 256>>>(a_idx, a_vals, bx, out);
}